// round 10
// baseline (speedup 1.0000x reference)
#include <cuda_runtime.h>
#include <cuda_fp16.h>
#include <math.h>
#include <stdint.h>

#define BATCH 2
#define SEQ   2048
#define DIM   1024
#define HEADS 16
#define DH    64
#define INNER 1024

// ---------------- scratch (device globals; no allocs) ----------------
__device__ __half g_h  [BATCH*SEQ*DIM];           // LN output (fp16)
__device__ float  g_qkv[BATCH*3*INNER*SEQ];       // (B, 3*INNER, SEQ) fp32
__device__ __half g_q16[BATCH*HEADS*SEQ*DH];      // [b][h][n][dh], scaled
__device__ __half g_k16[BATCH*HEADS*SEQ*DH];      // [b][h][n][dh]
__device__ __half g_v16[BATCH*HEADS*DH*SEQ];      // [b][h][dh][n]
__device__ __half g_ao [BATCH*SEQ*INNER];         // attention out (fp16)
__device__ __half g_wqkv[3*INNER*DIM];            // fp16 weights
__device__ __half g_wout[DIM*INNER];

// ---------------- helpers ----------------
__device__ __forceinline__ void mma_f16(float* d, const uint32_t* a, const uint32_t* b) {
    asm volatile(
        "mma.sync.aligned.m16n8k16.row.col.f32.f16.f16.f32 "
        "{%0,%1,%2,%3},{%4,%5,%6,%7},{%8,%9},{%0,%1,%2,%3};"
        : "+f"(d[0]), "+f"(d[1]), "+f"(d[2]), "+f"(d[3])
        : "r"(a[0]), "r"(a[1]), "r"(a[2]), "r"(a[3]), "r"(b[0]), "r"(b[1]));
}
__device__ __forceinline__ uint32_t pack_h2(float a, float b) {
    __half2 p = __floats2half2_rn(a, b);
    return *reinterpret_cast<uint32_t*>(&p);
}

// ---------------- fp16 pre-convert (weights) ----------------
__global__ __launch_bounds__(256) void cvt_f16_kernel(const float* __restrict__ src,
                                                      __half* __restrict__ dst, int n4) {
    int i = blockIdx.x * 256 + threadIdx.x;
    if (i >= n4) return;
    float4 v = reinterpret_cast<const float4*>(src)[i];
    reinterpret_cast<__half2*>(dst)[2*i]   = __floats2half2_rn(v.x, v.y);
    reinterpret_cast<__half2*>(dst)[2*i+1] = __floats2half2_rn(v.z, v.w);
}

// ---------------- LayerNorm (writes fp16) ----------------
__global__ __launch_bounds__(256) void ln_kernel(const float* __restrict__ x,
                                                 const float* __restrict__ gamma,
                                                 const float* __restrict__ beta) {
    int row = blockIdx.x;
    int tid = threadIdx.x;
    const float4* xr = reinterpret_cast<const float4*>(x) + (size_t)row * (DIM/4);
    float4 t = xr[tid];
    float s  = t.x + t.y + t.z + t.w;
    float ss = t.x*t.x + t.y*t.y + t.z*t.z + t.w*t.w;
    #pragma unroll
    for (int o = 16; o > 0; o >>= 1) {
        s  += __shfl_xor_sync(0xffffffffu, s,  o);
        ss += __shfl_xor_sync(0xffffffffu, ss, o);
    }
    __shared__ float ws[8], wss[8];
    int w = tid >> 5, l = tid & 31;
    if (l == 0) { ws[w] = s; wss[w] = ss; }
    __syncthreads();
    if (w == 0) {
        float a = (l < 8) ? ws[l]  : 0.f;
        float b = (l < 8) ? wss[l] : 0.f;
        #pragma unroll
        for (int o = 4; o > 0; o >>= 1) {
            a += __shfl_xor_sync(0xffffffffu, a, o);
            b += __shfl_xor_sync(0xffffffffu, b, o);
        }
        if (l == 0) { ws[0] = a; wss[0] = b; }
    }
    __syncthreads();
    float mu  = ws[0]  * (1.f / DIM);
    float var = wss[0] * (1.f / DIM) - mu * mu;
    float r   = rsqrtf(var + 1e-5f);
    float4 gm = reinterpret_cast<const float4*>(gamma)[tid];
    float4 bt = reinterpret_cast<const float4*>(beta)[tid];
    reinterpret_cast<__half2*>(g_h)[(size_t)row * (DIM/2) + 2*tid] =
        __floats2half2_rn((t.x - mu) * r * gm.x + bt.x, (t.y - mu) * r * gm.y + bt.y);
    reinterpret_cast<__half2*>(g_h)[(size_t)row * (DIM/2) + 2*tid+1] =
        __floats2half2_rn((t.z - mu) * r * gm.z + bt.z, (t.w - mu) * r * gm.w + bt.w);
}

// ---------------- FP16 GEMM-NT, BK=64, register-prefetch pipeline ----------------
// C[m][n] = sum_k A[m][k]*B[n][k]; A,B fp16, C fp32. BM=BN=128, 256 threads.
#define GST 36   // smem row stride in uint32 (32 data + 4 pad)
__global__ __launch_bounds__(256) void gemm_nt_f16(const __half* __restrict__ A,
                                                   const __half* __restrict__ B,
                                                   float* __restrict__ C,
                                                   int M, int N, int K,
                                                   long strideB, long strideC) {
    __shared__ __align__(16) uint32_t As[128 * GST];
    __shared__ __align__(16) uint32_t Bs[128 * GST];
    const __half* Bz = B + (size_t)blockIdx.z * strideB;
    float*        Cz = C + (size_t)blockIdx.z * strideC;
    int m0 = blockIdx.y * 128, n0 = blockIdx.x * 128;
    int tid = threadIdx.x, lane = tid & 31, wid = tid >> 5;
    int wm = (wid & 1) * 64, wn = (wid >> 1) * 32;
    int g = lane >> 2, t = lane & 3;
    float acc[4][4][4] = {};

    int r_ld = tid >> 1;                 // row 0..127
    int h_ld = (tid & 1) * 32;           // half offset within 64-wide row
    int u_ld = (tid & 1) * 16;           // uint32 offset in smem row

    float4 ra[4], rb[4];
    auto ld = [&](int k0) {
        const float4* pa = reinterpret_cast<const float4*>(A  + (size_t)(m0 + r_ld) * K + k0 + h_ld);
        ra[0] = pa[0]; ra[1] = pa[1]; ra[2] = pa[2]; ra[3] = pa[3];
        const float4* pb = reinterpret_cast<const float4*>(Bz + (size_t)(n0 + r_ld) * K + k0 + h_ld);
        rb[0] = pb[0]; rb[1] = pb[1]; rb[2] = pb[2]; rb[3] = pb[3];
    };
    auto st = [&]() {
        float4* da = reinterpret_cast<float4*>(&As[r_ld * GST + u_ld]);
        da[0] = ra[0]; da[1] = ra[1]; da[2] = ra[2]; da[3] = ra[3];
        float4* db = reinterpret_cast<float4*>(&Bs[r_ld * GST + u_ld]);
        db[0] = rb[0]; db[1] = rb[1]; db[2] = rb[2]; db[3] = rb[3];
    };

    ld(0);
    for (int k0 = 0; k0 < K; k0 += 64) {
        st();
        __syncthreads();
        if (k0 + 64 < K) ld(k0 + 64);    // prefetch next tile into registers
        #pragma unroll
        for (int ks = 0; ks < 32; ks += 8) {   // 4 x k16 mma steps
            uint32_t aR[4][4], bR[4][2];
            #pragma unroll
            for (int mf = 0; mf < 4; mf++) {
                int mb = wm + mf * 16;
                aR[mf][0] = As[(mb + g    ) * GST + ks + t    ];
                aR[mf][1] = As[(mb + g + 8) * GST + ks + t    ];
                aR[mf][2] = As[(mb + g    ) * GST + ks + t + 4];
                aR[mf][3] = As[(mb + g + 8) * GST + ks + t + 4];
            }
            #pragma unroll
            for (int nf = 0; nf < 4; nf++) {
                int nb = wn + nf * 8;
                bR[nf][0] = Bs[(nb + g) * GST + ks + t    ];
                bR[nf][1] = Bs[(nb + g) * GST + ks + t + 4];
            }
            #pragma unroll
            for (int mf = 0; mf < 4; mf++)
                #pragma unroll
                for (int nf = 0; nf < 4; nf++)
                    mma_f16(acc[mf][nf], aR[mf], bR[nf]);
        }
        __syncthreads();
    }

    #pragma unroll
    for (int mf = 0; mf < 4; mf++)
        #pragma unroll
        for (int nf = 0; nf < 4; nf++) {
            int m = m0 + wm + mf * 16 + g;
            int n = n0 + wn + nf * 8 + 2 * t;
            *reinterpret_cast<float2*>(Cz + (size_t)m * N + n) =
                make_float2(acc[mf][nf][0], acc[mf][nf][1]);
            *reinterpret_cast<float2*>(Cz + (size_t)(m + 8) * N + n) =
                make_float2(acc[mf][nf][2], acc[mf][nf][3]);
        }
}

// ---------------- tiled depthwise causal conv (fp16 out, mma layouts) ----------------
__device__ const float* g_convw[18];
__global__ __launch_bounds__(256) void conv_kernel() {
    __shared__ float  s_in [64 * 72];     // [dh][col], col = n0-8 .. n0+63
    __shared__ __half s_out[64 * 72];     // p<2: [n][dh]; p==2: [dh][n]
    int n0 = blockIdx.x * 64;
    int ct = blockIdx.y;                  // 0..47
    int p  = ct >> 4, h = ct & 15;
    int b  = blockIdx.z;
    int g  = h >> 2;
    int tid = threadIdx.x;

    const float* src = g_qkv + ((size_t)(b * 3 + p) * INNER + h * 64) * SEQ;
    for (int idx = tid; idx < 64 * 72; idx += 256) {
        int dh = idx / 72, col = idx % 72;
        int m = n0 - 8 + col;
        s_in[idx] = (m >= 0) ? src[(size_t)dh * SEQ + m] : 0.f;
    }
    __syncthreads();

    int dh = tid >> 2, nb = (tid & 3) * 16;
    float scale = (p == 0) ? 0.125f : 1.0f;
    if (g == 0) {
        for (int s = 0; s < 16; s++) {
            int rel = nb + s;
            float acc = s_in[dh * 72 + 8 + rel] * scale;
            if (p < 2) s_out[rel * 72 + dh] = __float2half(acc);
            else       s_out[dh * 72 + rel] = __float2half(acc);
        }
    } else {
        int ksz = 2 * g + 1;
        int cg  = (h & 3) * 64 + dh;
        const float* w  = g_convw[p * 6 + (g - 1) * 2] + cg * ksz;
        float bias      = g_convw[p * 6 + (g - 1) * 2 + 1][cg];
        float wr[7];
        for (int tt = 0; tt < ksz; tt++) wr[tt] = w[tt];
        for (int s = 0; s < 16; s++) {
            int rel = nb + s;
            float acc = bias;
            int cbase = dh * 72 + 8 + rel - (ksz - 1);
            for (int tt = 0; tt < ksz; tt++) acc += wr[tt] * s_in[cbase + tt];
            acc *= scale;
            if (p < 2) s_out[rel * 72 + dh] = __float2half(acc);
            else       s_out[dh * 72 + rel] = __float2half(acc);
        }
    }
    __syncthreads();

    int row = tid >> 2, chunk = tid & 3;
    const uint4* sp = reinterpret_cast<const uint4*>(&s_out[row * 72 + chunk * 16]);
    __half* dst;
    if (p < 2) {
        __half* base = (p == 0) ? g_q16 : g_k16;
        dst = base + ((size_t)(b * HEADS + h) * SEQ + n0 + row) * DH + chunk * 16;
    } else {
        dst = g_v16 + ((size_t)(b * HEADS + h) * DH + row) * SEQ + n0 + chunk * 16;
    }
    reinterpret_cast<uint4*>(dst)[0] = sp[0];
    reinterpret_cast<uint4*>(dst)[1] = sp[1];
}

__global__ void set_convw(const float* a0, const float* a1, const float* a2, const float* a3,
                          const float* a4, const float* a5, const float* a6, const float* a7,
                          const float* a8, const float* a9, const float* a10, const float* a11,
                          const float* a12, const float* a13, const float* a14, const float* a15,
                          const float* a16, const float* a17) {
    g_convw[0]=a0; g_convw[1]=a1; g_convw[2]=a2; g_convw[3]=a3; g_convw[4]=a4; g_convw[5]=a5;
    g_convw[6]=a6; g_convw[7]=a7; g_convw[8]=a8; g_convw[9]=a9; g_convw[10]=a10; g_convw[11]=a11;
    g_convw[12]=a12; g_convw[13]=a13; g_convw[14]=a14; g_convw[15]=a15; g_convw[16]=a16; g_convw[17]=a17;
}

// ---------------- fp16 tensor-core flash attention ----------------
// Q,K [bh][n][dh]; V [bh][dh][n]. 64 rows/block, 64-col tiles, 4 warps.
// Heaviest tiles scheduled first (reversed blockIdx.x).
#define AST 72
__global__ __launch_bounds__(128) void attn_f16(const float* __restrict__ slopes) {
    __shared__ __align__(16) __half Ksh[64 * AST];   // [j][d]
    __shared__ __align__(16) __half Vsh[64 * AST];   // [d][j]

    int it = gridDim.x - 1 - blockIdx.x;             // heavy CTAs first
    int i0 = it * 64;
    int bh = blockIdx.y, b = bh >> 4, h = bh & 15;
    float slope = slopes[h];
    int tid = threadIdx.x, lane = tid & 31, w = tid >> 5;
    int g = lane >> 2, t = lane & 3;
    int mb = w * 16;
    const __half* Qg = g_q16 + (size_t)bh * SEQ * DH;
    const __half* Kg = g_k16 + (size_t)bh * SEQ * DH;
    const __half* Vg = g_v16 + (size_t)bh * DH * SEQ;

    uint32_t aQ[4][4];
    int iq0 = i0 + mb + g, iq1 = iq0 + 8;
    #pragma unroll
    for (int ks = 0; ks < 4; ks++) {
        int base = ks * 16 + 2 * t;
        aQ[ks][0] = *reinterpret_cast<const uint32_t*>(&Qg[(size_t)iq0 * DH + base]);
        aQ[ks][1] = *reinterpret_cast<const uint32_t*>(&Qg[(size_t)iq1 * DH + base]);
        aQ[ks][2] = *reinterpret_cast<const uint32_t*>(&Qg[(size_t)iq0 * DH + base + 8]);
        aQ[ks][3] = *reinterpret_cast<const uint32_t*>(&Qg[(size_t)iq1 * DH + base + 8]);
    }

    float o[8][4] = {};
    float m0 = -1e30f, m1 = -1e30f, l0 = 0.f, l1 = 0.f;

    for (int jt = 0; jt <= it; jt++) {
        int j0 = jt * 64;
        __syncthreads();
        {
            int r = tid >> 1, c = (tid & 1) * 32;
            const uint4* ks_ = reinterpret_cast<const uint4*>(&Kg[(size_t)(j0 + r) * DH + c]);
            uint4* kd = reinterpret_cast<uint4*>(&Ksh[r * AST + c]);
            kd[0] = ks_[0]; kd[1] = ks_[1]; kd[2] = ks_[2]; kd[3] = ks_[3];
            const uint4* vs_ = reinterpret_cast<const uint4*>(&Vg[(size_t)r * SEQ + j0 + c]);
            uint4* vd = reinterpret_cast<uint4*>(&Vsh[r * AST + c]);
            vd[0] = vs_[0]; vd[1] = vs_[1]; vd[2] = vs_[2]; vd[3] = vs_[3];
        }
        __syncthreads();

        float sF[8][4] = {};
        #pragma unroll
        for (int ks = 0; ks < 4; ks++) {
            #pragma unroll
            for (int nf = 0; nf < 8; nf++) {
                uint32_t bR[2];
                const __half* kp = &Ksh[(nf*8 + g) * AST + ks * 16 + 2 * t];
                bR[0] = *reinterpret_cast<const uint32_t*>(kp);
                bR[1] = *reinterpret_cast<const uint32_t*>(kp + 8);
                mma_f16(sF[nf], aQ[ks], bR);
            }
        }

        int ir0 = i0 + mb + g, ir1 = ir0 + 8;
        float mloc0 = -1e30f, mloc1 = -1e30f;
        #pragma unroll
        for (int nf = 0; nf < 8; nf++) {
            int jc = j0 + nf*8 + 2*t;
            float v0 = sF[nf][0] + slope * (float)(jc     - ir0);
            float v1 = sF[nf][1] + slope * (float)(jc + 1 - ir0);
            float v2 = sF[nf][2] + slope * (float)(jc     - ir1);
            float v3 = sF[nf][3] + slope * (float)(jc + 1 - ir1);
            if (jc     > ir0) v0 = -1e30f;
            if (jc + 1 > ir0) v1 = -1e30f;
            if (jc     > ir1) v2 = -1e30f;
            if (jc + 1 > ir1) v3 = -1e30f;
            sF[nf][0] = v0; sF[nf][1] = v1; sF[nf][2] = v2; sF[nf][3] = v3;
            mloc0 = fmaxf(mloc0, fmaxf(v0, v1));
            mloc1 = fmaxf(mloc1, fmaxf(v2, v3));
        }
        mloc0 = fmaxf(mloc0, __shfl_xor_sync(0xffffffffu, mloc0, 1));
        mloc0 = fmaxf(mloc0, __shfl_xor_sync(0xffffffffu, mloc0, 2));
        mloc1 = fmaxf(mloc1, __shfl_xor_sync(0xffffffffu, mloc1, 1));
        mloc1 = fmaxf(mloc1, __shfl_xor_sync(0xffffffffu, mloc1, 2));
        float mn0 = fmaxf(m0, mloc0), mn1 = fmaxf(m1, mloc1);
        float sc0 = __expf(m0 - mn0), sc1 = __expf(m1 - mn1);
        float sum0 = 0.f, sum1 = 0.f;
        #pragma unroll
        for (int nf = 0; nf < 8; nf++) {
            sF[nf][0] = __expf(sF[nf][0] - mn0); sum0 += sF[nf][0];
            sF[nf][1] = __expf(sF[nf][1] - mn0); sum0 += sF[nf][1];
            sF[nf][2] = __expf(sF[nf][2] - mn1); sum1 += sF[nf][2];
            sF[nf][3] = __expf(sF[nf][3] - mn1); sum1 += sF[nf][3];
        }
        sum0 += __shfl_xor_sync(0xffffffffu, sum0, 1);
        sum0 += __shfl_xor_sync(0xffffffffu, sum0, 2);
        sum1 += __shfl_xor_sync(0xffffffffu, sum1, 1);
        sum1 += __shfl_xor_sync(0xffffffffu, sum1, 2);
        l0 = l0 * sc0 + sum0; l1 = l1 * sc1 + sum1;
        m0 = mn0; m1 = mn1;
        #pragma unroll
        for (int nf = 0; nf < 8; nf++) {
            o[nf][0] *= sc0; o[nf][1] *= sc0;
            o[nf][2] *= sc1; o[nf][3] *= sc1;
        }

        uint32_t aP[4][4];
        #pragma unroll
        for (int ks = 0; ks < 4; ks++) {
            aP[ks][0] = pack_h2(sF[2*ks  ][0], sF[2*ks  ][1]);
            aP[ks][1] = pack_h2(sF[2*ks  ][2], sF[2*ks  ][3]);
            aP[ks][2] = pack_h2(sF[2*ks+1][0], sF[2*ks+1][1]);
            aP[ks][3] = pack_h2(sF[2*ks+1][2], sF[2*ks+1][3]);
        }

        #pragma unroll
        for (int ks = 0; ks < 4; ks++) {
            #pragma unroll
            for (int nf = 0; nf < 8; nf++) {
                uint32_t bR[2];
                const __half* vp = &Vsh[(nf*8 + g) * AST + ks * 16 + 2 * t];
                bR[0] = *reinterpret_cast<const uint32_t*>(vp);
                bR[1] = *reinterpret_cast<const uint32_t*>(vp + 8);
                mma_f16(o[nf], aP[ks], bR);
            }
        }
    }

    float inv0 = 1.f / l0, inv1 = 1.f / l1;
    int r0 = i0 + mb + g;
    #pragma unroll
    for (int nf = 0; nf < 8; nf++) {
        int col = h * DH + nf*8 + 2*t;
        *reinterpret_cast<__half2*>(&g_ao[((size_t)b * SEQ + r0    ) * INNER + col]) =
            __floats2half2_rn(o[nf][0] * inv0, o[nf][1] * inv0);
        *reinterpret_cast<__half2*>(&g_ao[((size_t)b * SEQ + r0 + 8) * INNER + col]) =
            __floats2half2_rn(o[nf][2] * inv1, o[nf][3] * inv1);
    }
}

// ---------------- launch ----------------
extern "C" void kernel_launch(void* const* d_in, const int* in_sizes, int n_in,
                              void* d_out, int out_size) {
    const float* x      = (const float*)d_in[0];
    const float* gamma  = (const float*)d_in[1];
    const float* beta   = (const float*)d_in[2];
    const float* w_qkv  = (const float*)d_in[3];
    const float* slopes = (const float*)d_in[22];
    const float* w_out  = (const float*)d_in[23];

    __half *ph, *pao, *pwqkv, *pwout;
    float *pqkv;
    cudaGetSymbolAddress((void**)&ph,    g_h);
    cudaGetSymbolAddress((void**)&pqkv,  g_qkv);
    cudaGetSymbolAddress((void**)&pao,   g_ao);
    cudaGetSymbolAddress((void**)&pwqkv, g_wqkv);
    cudaGetSymbolAddress((void**)&pwout, g_wout);

    // 0) conv weight ptrs + fp16 weight conversion
    set_convw<<<1, 1>>>(
        (const float*)d_in[4],  (const float*)d_in[5],  (const float*)d_in[6],
        (const float*)d_in[7],  (const float*)d_in[8],  (const float*)d_in[9],
        (const float*)d_in[10], (const float*)d_in[11], (const float*)d_in[12],
        (const float*)d_in[13], (const float*)d_in[14], (const float*)d_in[15],
        (const float*)d_in[16], (const float*)d_in[17], (const float*)d_in[18],
        (const float*)d_in[19], (const float*)d_in[20], (const float*)d_in[21]);
    cvt_f16_kernel<<<(3*INNER*DIM/4 + 255)/256, 256>>>(w_qkv, pwqkv, 3*INNER*DIM/4);
    cvt_f16_kernel<<<(DIM*INNER/4   + 255)/256, 256>>>(w_out, pwout, DIM*INNER/4);

    // 1) LayerNorm (fp16 out)
    ln_kernel<<<BATCH * SEQ, 256>>>(x, gamma, beta);

    // 2) QKV GEMM (fp16 in, fp32 out), BK=64 reg-prefetch pipeline
    gemm_nt_f16<<<dim3(SEQ/128, 3*INNER/128, BATCH), 256>>>(
        pwqkv, ph, pqkv, 3*INNER, SEQ, DIM,
        (long)SEQ * DIM, (long)3 * INNER * SEQ);

    // 3) tiled depthwise causal convs -> fp16 q/k [n][dh], v [dh][n]
    conv_kernel<<<dim3(SEQ/64, 48, BATCH), 256>>>();

    // 4) fp16 tensor-core flash attention (heavy CTAs first)
    attn_f16<<<dim3(SEQ/64, BATCH*HEADS), 128>>>(slopes);

    // 5) output projection (fp16 in, fp32 out)
    gemm_nt_f16<<<dim3(DIM/128, (BATCH*SEQ)/128, 1), 256>>>(
        pao, pwout, (float*)d_out, BATCH*SEQ, DIM, INNER, 0, 0);
}

// round 11
// speedup vs baseline: 1.0107x; 1.0107x over previous
#include <cuda_runtime.h>
#include <cuda_fp16.h>
#include <math.h>
#include <stdint.h>

#define BATCH 2
#define SEQ   2048
#define DIM   1024
#define HEADS 16
#define DH    64
#define INNER 1024

// ---------------- scratch (device globals; no allocs) ----------------
__device__ __half g_h  [BATCH*SEQ*DIM];           // LN output (fp16)
__device__ float  g_qkv[BATCH*3*INNER*SEQ];       // (B, 3*INNER, SEQ) fp32
__device__ __half g_q16[BATCH*HEADS*SEQ*DH];      // [b][h][n][dh], scaled
__device__ __half g_k16[BATCH*HEADS*SEQ*DH];      // [b][h][n][dh]
__device__ __half g_v16[BATCH*HEADS*DH*SEQ];      // [b][h][dh][n]
__device__ __half g_ao [BATCH*SEQ*INNER];         // attention out (fp16)
__device__ __half g_wqkv[3*INNER*DIM];            // fp16 weights
__device__ __half g_wout[DIM*INNER];

// ---------------- helpers ----------------
__device__ __forceinline__ void mma_f16(float* d, const uint32_t* a, const uint32_t* b) {
    asm volatile(
        "mma.sync.aligned.m16n8k16.row.col.f32.f16.f16.f32 "
        "{%0,%1,%2,%3},{%4,%5,%6,%7},{%8,%9},{%0,%1,%2,%3};"
        : "+f"(d[0]), "+f"(d[1]), "+f"(d[2]), "+f"(d[3])
        : "r"(a[0]), "r"(a[1]), "r"(a[2]), "r"(a[3]), "r"(b[0]), "r"(b[1]));
}
__device__ __forceinline__ uint32_t pack_h2(float a, float b) {
    __half2 p = __floats2half2_rn(a, b);
    return *reinterpret_cast<uint32_t*>(&p);
}

// ---------------- fp16 pre-convert (weights) ----------------
__global__ __launch_bounds__(256) void cvt_f16_kernel(const float* __restrict__ src,
                                                      __half* __restrict__ dst, int n4) {
    int i = blockIdx.x * 256 + threadIdx.x;
    if (i >= n4) return;
    float4 v = reinterpret_cast<const float4*>(src)[i];
    reinterpret_cast<__half2*>(dst)[2*i]   = __floats2half2_rn(v.x, v.y);
    reinterpret_cast<__half2*>(dst)[2*i+1] = __floats2half2_rn(v.z, v.w);
}

// ---------------- LayerNorm (writes fp16) ----------------
__global__ __launch_bounds__(256) void ln_kernel(const float* __restrict__ x,
                                                 const float* __restrict__ gamma,
                                                 const float* __restrict__ beta) {
    int row = blockIdx.x;
    int tid = threadIdx.x;
    const float4* xr = reinterpret_cast<const float4*>(x) + (size_t)row * (DIM/4);
    float4 t = xr[tid];
    float s  = t.x + t.y + t.z + t.w;
    float ss = t.x*t.x + t.y*t.y + t.z*t.z + t.w*t.w;
    #pragma unroll
    for (int o = 16; o > 0; o >>= 1) {
        s  += __shfl_xor_sync(0xffffffffu, s,  o);
        ss += __shfl_xor_sync(0xffffffffu, ss, o);
    }
    __shared__ float ws[8], wss[8];
    int w = tid >> 5, l = tid & 31;
    if (l == 0) { ws[w] = s; wss[w] = ss; }
    __syncthreads();
    if (w == 0) {
        float a = (l < 8) ? ws[l]  : 0.f;
        float b = (l < 8) ? wss[l] : 0.f;
        #pragma unroll
        for (int o = 4; o > 0; o >>= 1) {
            a += __shfl_xor_sync(0xffffffffu, a, o);
            b += __shfl_xor_sync(0xffffffffu, b, o);
        }
        if (l == 0) { ws[0] = a; wss[0] = b; }
    }
    __syncthreads();
    float mu  = ws[0]  * (1.f / DIM);
    float var = wss[0] * (1.f / DIM) - mu * mu;
    float r   = rsqrtf(var + 1e-5f);
    float4 gm = reinterpret_cast<const float4*>(gamma)[tid];
    float4 bt = reinterpret_cast<const float4*>(beta)[tid];
    reinterpret_cast<__half2*>(g_h)[(size_t)row * (DIM/2) + 2*tid] =
        __floats2half2_rn((t.x - mu) * r * gm.x + bt.x, (t.y - mu) * r * gm.y + bt.y);
    reinterpret_cast<__half2*>(g_h)[(size_t)row * (DIM/2) + 2*tid+1] =
        __floats2half2_rn((t.z - mu) * r * gm.z + bt.z, (t.w - mu) * r * gm.w + bt.w);
}

// ---------------- FP16 GEMM-NT (proven R8/R9 form: BK=32, single-buffered) ----------------
__global__ __launch_bounds__(256) void gemm_nt_f16(const __half* __restrict__ A,
                                                   const __half* __restrict__ B,
                                                   float* __restrict__ C,
                                                   int M, int N, int K,
                                                   long strideB, long strideC) {
    __shared__ __align__(16) uint32_t As[128 * 20];
    __shared__ __align__(16) uint32_t Bs[128 * 20];
    const __half* Bz = B + (size_t)blockIdx.z * strideB;
    float*        Cz = C + (size_t)blockIdx.z * strideC;
    int m0 = blockIdx.y * 128, n0 = blockIdx.x * 128;
    int tid = threadIdx.x, lane = tid & 31, wid = tid >> 5;
    int wm = (wid & 1) * 64, wn = (wid >> 1) * 32;
    int g = lane >> 2, t = lane & 3;
    float acc[4][4][4] = {};

    for (int k0 = 0; k0 < K; k0 += 32) {
        #pragma unroll
        for (int i = 0; i < 2; i++) {
            int f = tid + 256 * i;
            int r = f >> 2, c4 = f & 3;
            float4 a = *reinterpret_cast<const float4*>(A  + (size_t)(m0 + r) * K + k0 + c4 * 8);
            *reinterpret_cast<float4*>(&As[r * 20 + c4 * 4]) = a;
            float4 b = *reinterpret_cast<const float4*>(Bz + (size_t)(n0 + r) * K + k0 + c4 * 8);
            *reinterpret_cast<float4*>(&Bs[r * 20 + c4 * 4]) = b;
        }
        __syncthreads();
        #pragma unroll
        for (int ks = 0; ks < 16; ks += 8) {
            uint32_t aR[4][4], bR[4][2];
            #pragma unroll
            for (int mf = 0; mf < 4; mf++) {
                int mb = wm + mf * 16;
                aR[mf][0] = As[(mb + g    ) * 20 + ks + t    ];
                aR[mf][1] = As[(mb + g + 8) * 20 + ks + t    ];
                aR[mf][2] = As[(mb + g    ) * 20 + ks + t + 4];
                aR[mf][3] = As[(mb + g + 8) * 20 + ks + t + 4];
            }
            #pragma unroll
            for (int nf = 0; nf < 4; nf++) {
                int nb = wn + nf * 8;
                bR[nf][0] = Bs[(nb + g) * 20 + ks + t    ];
                bR[nf][1] = Bs[(nb + g) * 20 + ks + t + 4];
            }
            #pragma unroll
            for (int mf = 0; mf < 4; mf++)
                #pragma unroll
                for (int nf = 0; nf < 4; nf++)
                    mma_f16(acc[mf][nf], aR[mf], bR[nf]);
        }
        __syncthreads();
    }

    #pragma unroll
    for (int mf = 0; mf < 4; mf++)
        #pragma unroll
        for (int nf = 0; nf < 4; nf++) {
            int m = m0 + wm + mf * 16 + g;
            int n = n0 + wn + nf * 8 + 2 * t;
            *reinterpret_cast<float2*>(Cz + (size_t)m * N + n) =
                make_float2(acc[mf][nf][0], acc[mf][nf][1]);
            *reinterpret_cast<float2*>(Cz + (size_t)(m + 8) * N + n) =
                make_float2(acc[mf][nf][2], acc[mf][nf][3]);
        }
}

// ---------------- tiled depthwise causal conv (fp16 out, mma layouts) ----------------
__device__ const float* g_convw[18];
__global__ __launch_bounds__(256) void conv_kernel() {
    __shared__ float  s_in [64 * 72];     // [dh][col], col = n0-8 .. n0+63
    __shared__ __half s_out[64 * 72];     // p<2: [n][dh]; p==2: [dh][n]
    int n0 = blockIdx.x * 64;
    int ct = blockIdx.y;                  // 0..47
    int p  = ct >> 4, h = ct & 15;
    int b  = blockIdx.z;
    int g  = h >> 2;
    int tid = threadIdx.x;

    const float* src = g_qkv + ((size_t)(b * 3 + p) * INNER + h * 64) * SEQ;
    for (int idx = tid; idx < 64 * 72; idx += 256) {
        int dh = idx / 72, col = idx % 72;
        int m = n0 - 8 + col;
        s_in[idx] = (m >= 0) ? src[(size_t)dh * SEQ + m] : 0.f;
    }
    __syncthreads();

    int dh = tid >> 2, nb = (tid & 3) * 16;
    float scale = (p == 0) ? 0.125f : 1.0f;
    if (g == 0) {
        for (int s = 0; s < 16; s++) {
            int rel = nb + s;
            float acc = s_in[dh * 72 + 8 + rel] * scale;
            if (p < 2) s_out[rel * 72 + dh] = __float2half(acc);
            else       s_out[dh * 72 + rel] = __float2half(acc);
        }
    } else {
        int ksz = 2 * g + 1;
        int cg  = (h & 3) * 64 + dh;
        const float* w  = g_convw[p * 6 + (g - 1) * 2] + cg * ksz;
        float bias      = g_convw[p * 6 + (g - 1) * 2 + 1][cg];
        float wr[7];
        for (int tt = 0; tt < ksz; tt++) wr[tt] = w[tt];
        for (int s = 0; s < 16; s++) {
            int rel = nb + s;
            float acc = bias;
            int cbase = dh * 72 + 8 + rel - (ksz - 1);
            for (int tt = 0; tt < ksz; tt++) acc += wr[tt] * s_in[cbase + tt];
            acc *= scale;
            if (p < 2) s_out[rel * 72 + dh] = __float2half(acc);
            else       s_out[dh * 72 + rel] = __float2half(acc);
        }
    }
    __syncthreads();

    int row = tid >> 2, chunk = tid & 3;
    const uint4* sp = reinterpret_cast<const uint4*>(&s_out[row * 72 + chunk * 16]);
    __half* dst;
    if (p < 2) {
        __half* base = (p == 0) ? g_q16 : g_k16;
        dst = base + ((size_t)(b * HEADS + h) * SEQ + n0 + row) * DH + chunk * 16;
    } else {
        dst = g_v16 + ((size_t)(b * HEADS + h) * DH + row) * SEQ + n0 + chunk * 16;
    }
    reinterpret_cast<uint4*>(dst)[0] = sp[0];
    reinterpret_cast<uint4*>(dst)[1] = sp[1];
}

__global__ void set_convw(const float* a0, const float* a1, const float* a2, const float* a3,
                          const float* a4, const float* a5, const float* a6, const float* a7,
                          const float* a8, const float* a9, const float* a10, const float* a11,
                          const float* a12, const float* a13, const float* a14, const float* a15,
                          const float* a16, const float* a17) {
    g_convw[0]=a0; g_convw[1]=a1; g_convw[2]=a2; g_convw[3]=a3; g_convw[4]=a4; g_convw[5]=a5;
    g_convw[6]=a6; g_convw[7]=a7; g_convw[8]=a8; g_convw[9]=a9; g_convw[10]=a10; g_convw[11]=a11;
    g_convw[12]=a12; g_convw[13]=a13; g_convw[14]=a14; g_convw[15]=a15; g_convw[16]=a16; g_convw[17]=a17;
}

// ---------------- fp16 tensor-core flash attention, BM=128, 8 warps ----------------
// Q,K [bh][n][dh]; V [bh][dh][n]. 128 query rows per CTA, 64-col K/V tiles shared
// by 8 warps. P in registers, Q frags from gmem, 18KB smem. Heavy CTAs first.
#define AST 72
__global__ __launch_bounds__(256) void attn_f16(const float* __restrict__ slopes) {
    __shared__ __align__(16) __half Ksh[64 * AST];   // [j][d]
    __shared__ __align__(16) __half Vsh[64 * AST];   // [d][j]

    int it = gridDim.x - 1 - blockIdx.x;             // heavy CTAs first
    int i0 = it * 128;
    int bh = blockIdx.y, b = bh >> 4, h = bh & 15;
    float slope = slopes[h];
    int tid = threadIdx.x, lane = tid & 31, w = tid >> 5;
    int g = lane >> 2, t = lane & 3;
    int mb = w * 16;                                 // warp rows [mb, mb+16) of 128
    const __half* Qg = g_q16 + (size_t)bh * SEQ * DH;
    const __half* Kg = g_k16 + (size_t)bh * SEQ * DH;
    const __half* Vg = g_v16 + (size_t)bh * DH * SEQ;

    // Q fragments straight from gmem
    uint32_t aQ[4][4];
    int iq0 = i0 + mb + g, iq1 = iq0 + 8;
    #pragma unroll
    for (int ks = 0; ks < 4; ks++) {
        int base = ks * 16 + 2 * t;
        aQ[ks][0] = *reinterpret_cast<const uint32_t*>(&Qg[(size_t)iq0 * DH + base]);
        aQ[ks][1] = *reinterpret_cast<const uint32_t*>(&Qg[(size_t)iq1 * DH + base]);
        aQ[ks][2] = *reinterpret_cast<const uint32_t*>(&Qg[(size_t)iq0 * DH + base + 8]);
        aQ[ks][3] = *reinterpret_cast<const uint32_t*>(&Qg[(size_t)iq1 * DH + base + 8]);
    }

    float o[8][4] = {};
    float m0 = -1e30f, m1 = -1e30f, l0 = 0.f, l1 = 0.f;
    int jt_max = 2 * it + 1;

    for (int jt = 0; jt <= jt_max; jt++) {
        int j0 = jt * 64;
        __syncthreads();
        {   // 256 threads: half load K [j][d], half load V [d][j]
            int half = tid >> 7;
            int r = (tid & 127) >> 1, c = (tid & 1) * 32;
            if (half == 0) {
                const uint4* ks_ = reinterpret_cast<const uint4*>(&Kg[(size_t)(j0 + r) * DH + c]);
                uint4* kd = reinterpret_cast<uint4*>(&Ksh[r * AST + c]);
                kd[0] = ks_[0]; kd[1] = ks_[1]; kd[2] = ks_[2]; kd[3] = ks_[3];
            } else {
                const uint4* vs_ = reinterpret_cast<const uint4*>(&Vg[(size_t)r * SEQ + j0 + c]);
                uint4* vd = reinterpret_cast<uint4*>(&Vsh[r * AST + c]);
                vd[0] = vs_[0]; vd[1] = vs_[1]; vd[2] = vs_[2]; vd[3] = vs_[3];
            }
        }
        __syncthreads();

        // S = Q K^T
        float sF[8][4] = {};
        #pragma unroll
        for (int ks = 0; ks < 4; ks++) {
            #pragma unroll
            for (int nf = 0; nf < 8; nf++) {
                uint32_t bR[2];
                const __half* kp = &Ksh[(nf*8 + g) * AST + ks * 16 + 2 * t];
                bR[0] = *reinterpret_cast<const uint32_t*>(kp);
                bR[1] = *reinterpret_cast<const uint32_t*>(kp + 8);
                mma_f16(sF[nf], aQ[ks], bR);
            }
        }

        // bias + causal mask + online softmax
        int ir0 = i0 + mb + g, ir1 = ir0 + 8;
        float mloc0 = -1e30f, mloc1 = -1e30f;
        #pragma unroll
        for (int nf = 0; nf < 8; nf++) {
            int jc = j0 + nf*8 + 2*t;
            float v0 = sF[nf][0] + slope * (float)(jc     - ir0);
            float v1 = sF[nf][1] + slope * (float)(jc + 1 - ir0);
            float v2 = sF[nf][2] + slope * (float)(jc     - ir1);
            float v3 = sF[nf][3] + slope * (float)(jc + 1 - ir1);
            if (jc     > ir0) v0 = -1e30f;
            if (jc + 1 > ir0) v1 = -1e30f;
            if (jc     > ir1) v2 = -1e30f;
            if (jc + 1 > ir1) v3 = -1e30f;
            sF[nf][0] = v0; sF[nf][1] = v1; sF[nf][2] = v2; sF[nf][3] = v3;
            mloc0 = fmaxf(mloc0, fmaxf(v0, v1));
            mloc1 = fmaxf(mloc1, fmaxf(v2, v3));
        }
        mloc0 = fmaxf(mloc0, __shfl_xor_sync(0xffffffffu, mloc0, 1));
        mloc0 = fmaxf(mloc0, __shfl_xor_sync(0xffffffffu, mloc0, 2));
        mloc1 = fmaxf(mloc1, __shfl_xor_sync(0xffffffffu, mloc1, 1));
        mloc1 = fmaxf(mloc1, __shfl_xor_sync(0xffffffffu, mloc1, 2));
        float mn0 = fmaxf(m0, mloc0), mn1 = fmaxf(m1, mloc1);
        float sc0 = __expf(m0 - mn0), sc1 = __expf(m1 - mn1);
        float sum0 = 0.f, sum1 = 0.f;
        #pragma unroll
        for (int nf = 0; nf < 8; nf++) {
            sF[nf][0] = __expf(sF[nf][0] - mn0); sum0 += sF[nf][0];
            sF[nf][1] = __expf(sF[nf][1] - mn0); sum0 += sF[nf][1];
            sF[nf][2] = __expf(sF[nf][2] - mn1); sum1 += sF[nf][2];
            sF[nf][3] = __expf(sF[nf][3] - mn1); sum1 += sF[nf][3];
        }
        sum0 += __shfl_xor_sync(0xffffffffu, sum0, 1);
        sum0 += __shfl_xor_sync(0xffffffffu, sum0, 2);
        sum1 += __shfl_xor_sync(0xffffffffu, sum1, 1);
        sum1 += __shfl_xor_sync(0xffffffffu, sum1, 2);
        l0 = l0 * sc0 + sum0; l1 = l1 * sc1 + sum1;
        m0 = mn0; m1 = mn1;
        #pragma unroll
        for (int nf = 0; nf < 8; nf++) {
            o[nf][0] *= sc0; o[nf][1] *= sc0;
            o[nf][2] *= sc1; o[nf][3] *= sc1;
        }

        // pack P into fp16 A-fragments (registers only)
        uint32_t aP[4][4];
        #pragma unroll
        for (int ks = 0; ks < 4; ks++) {
            aP[ks][0] = pack_h2(sF[2*ks  ][0], sF[2*ks  ][1]);
            aP[ks][1] = pack_h2(sF[2*ks  ][2], sF[2*ks  ][3]);
            aP[ks][2] = pack_h2(sF[2*ks+1][0], sF[2*ks+1][1]);
            aP[ks][3] = pack_h2(sF[2*ks+1][2], sF[2*ks+1][3]);
        }

        // O += P V
        #pragma unroll
        for (int ks = 0; ks < 4; ks++) {
            #pragma unroll
            for (int nf = 0; nf < 8; nf++) {
                uint32_t bR[2];
                const __half* vp = &Vsh[(nf*8 + g) * AST + ks * 16 + 2 * t];
                bR[0] = *reinterpret_cast<const uint32_t*>(vp);
                bR[1] = *reinterpret_cast<const uint32_t*>(vp + 8);
                mma_f16(o[nf], aP[ks], bR);
            }
        }
    }

    // normalize + write (B,N,INNER) as fp16
    float inv0 = 1.f / l0, inv1 = 1.f / l1;
    int r0 = i0 + mb + g;
    #pragma unroll
    for (int nf = 0; nf < 8; nf++) {
        int col = h * DH + nf*8 + 2*t;
        *reinterpret_cast<__half2*>(&g_ao[((size_t)b * SEQ + r0    ) * INNER + col]) =
            __floats2half2_rn(o[nf][0] * inv0, o[nf][1] * inv0);
        *reinterpret_cast<__half2*>(&g_ao[((size_t)b * SEQ + r0 + 8) * INNER + col]) =
            __floats2half2_rn(o[nf][2] * inv1, o[nf][3] * inv1);
    }
}

// ---------------- launch ----------------
extern "C" void kernel_launch(void* const* d_in, const int* in_sizes, int n_in,
                              void* d_out, int out_size) {
    const float* x      = (const float*)d_in[0];
    const float* gamma  = (const float*)d_in[1];
    const float* beta   = (const float*)d_in[2];
    const float* w_qkv  = (const float*)d_in[3];
    const float* slopes = (const float*)d_in[22];
    const float* w_out  = (const float*)d_in[23];

    __half *ph, *pao, *pwqkv, *pwout;
    float *pqkv;
    cudaGetSymbolAddress((void**)&ph,    g_h);
    cudaGetSymbolAddress((void**)&pqkv,  g_qkv);
    cudaGetSymbolAddress((void**)&pao,   g_ao);
    cudaGetSymbolAddress((void**)&pwqkv, g_wqkv);
    cudaGetSymbolAddress((void**)&pwout, g_wout);

    // 0) conv weight ptrs + fp16 weight conversion
    set_convw<<<1, 1>>>(
        (const float*)d_in[4],  (const float*)d_in[5],  (const float*)d_in[6],
        (const float*)d_in[7],  (const float*)d_in[8],  (const float*)d_in[9],
        (const float*)d_in[10], (const float*)d_in[11], (const float*)d_in[12],
        (const float*)d_in[13], (const float*)d_in[14], (const float*)d_in[15],
        (const float*)d_in[16], (const float*)d_in[17], (const float*)d_in[18],
        (const float*)d_in[19], (const float*)d_in[20], (const float*)d_in[21]);
    cvt_f16_kernel<<<(3*INNER*DIM/4 + 255)/256, 256>>>(w_qkv, pwqkv, 3*INNER*DIM/4);
    cvt_f16_kernel<<<(DIM*INNER/4   + 255)/256, 256>>>(w_out, pwout, DIM*INNER/4);

    // 1) LayerNorm (fp16 out)
    ln_kernel<<<BATCH * SEQ, 256>>>(x, gamma, beta);

    // 2) QKV GEMM (fp16 in, fp32 out)
    gemm_nt_f16<<<dim3(SEQ/128, 3*INNER/128, BATCH), 256>>>(
        pwqkv, ph, pqkv, 3*INNER, SEQ, DIM,
        (long)SEQ * DIM, (long)3 * INNER * SEQ);

    // 3) tiled depthwise causal convs -> fp16 q/k [n][dh], v [dh][n]
    conv_kernel<<<dim3(SEQ/64, 48, BATCH), 256>>>();

    // 4) fp16 tensor-core flash attention, BM=128, heavy CTAs first
    attn_f16<<<dim3(SEQ/128, BATCH*HEADS), 256>>>(slopes);

    // 5) output projection (fp16 in, fp32 out)
    gemm_nt_f16<<<dim3(DIM/128, (BATCH*SEQ)/128, 1), 256>>>(
        pao, pwout, (float*)d_out, BATCH*SEQ, DIM, INNER, 0, 0);
}

// round 12
// speedup vs baseline: 1.1162x; 1.1043x over previous
#include <cuda_runtime.h>
#include <cuda_fp16.h>
#include <math.h>
#include <stdint.h>

#define BATCH 2
#define SEQ   2048
#define DIM   1024
#define HEADS 16
#define DH    64
#define INNER 1024

// ---------------- scratch (device globals; no allocs) ----------------
__device__ __half g_h  [BATCH*SEQ*DIM];           // LN output (fp16)
__device__ float  g_qkv[BATCH*3*INNER*SEQ];       // (B, 3*INNER, SEQ) fp32
__device__ __half g_q16[BATCH*HEADS*SEQ*DH];      // [b][h][n][dh], scaled
__device__ __half g_k16[BATCH*HEADS*SEQ*DH];      // [b][h][n][dh]
__device__ __half g_v16[BATCH*HEADS*DH*SEQ];      // [b][h][dh][n]
__device__ __half g_ao [BATCH*SEQ*INNER];         // attention out (fp16)
__device__ __half g_wqkv[3*INNER*DIM];            // fp16 weights
__device__ __half g_wout[DIM*INNER];

// ---------------- helpers ----------------
__device__ __forceinline__ void mma_f16(float* d, const uint32_t* a, const uint32_t* b) {
    asm volatile(
        "mma.sync.aligned.m16n8k16.row.col.f32.f16.f16.f32 "
        "{%0,%1,%2,%3},{%4,%5,%6,%7},{%8,%9},{%0,%1,%2,%3};"
        : "+f"(d[0]), "+f"(d[1]), "+f"(d[2]), "+f"(d[3])
        : "r"(a[0]), "r"(a[1]), "r"(a[2]), "r"(a[3]), "r"(b[0]), "r"(b[1]));
}
__device__ __forceinline__ void ldsm_x4(uint32_t* r, uint32_t saddr) {
    asm volatile("ldmatrix.sync.aligned.m8n8.x4.shared.b16 {%0,%1,%2,%3}, [%4];"
        : "=r"(r[0]), "=r"(r[1]), "=r"(r[2]), "=r"(r[3]) : "r"(saddr));
}
__device__ __forceinline__ uint32_t pack_h2(float a, float b) {
    __half2 p = __floats2half2_rn(a, b);
    return *reinterpret_cast<uint32_t*>(&p);
}

// ---------------- fp16 pre-convert (weights) ----------------
__global__ __launch_bounds__(256) void cvt_f16_kernel(const float* __restrict__ src,
                                                      __half* __restrict__ dst, int n4) {
    int i = blockIdx.x * 256 + threadIdx.x;
    if (i >= n4) return;
    float4 v = reinterpret_cast<const float4*>(src)[i];
    reinterpret_cast<__half2*>(dst)[2*i]   = __floats2half2_rn(v.x, v.y);
    reinterpret_cast<__half2*>(dst)[2*i+1] = __floats2half2_rn(v.z, v.w);
}

// ---------------- LayerNorm (writes fp16) ----------------
__global__ __launch_bounds__(256) void ln_kernel(const float* __restrict__ x,
                                                 const float* __restrict__ gamma,
                                                 const float* __restrict__ beta) {
    int row = blockIdx.x;
    int tid = threadIdx.x;
    const float4* xr = reinterpret_cast<const float4*>(x) + (size_t)row * (DIM/4);
    float4 t = xr[tid];
    float s  = t.x + t.y + t.z + t.w;
    float ss = t.x*t.x + t.y*t.y + t.z*t.z + t.w*t.w;
    #pragma unroll
    for (int o = 16; o > 0; o >>= 1) {
        s  += __shfl_xor_sync(0xffffffffu, s,  o);
        ss += __shfl_xor_sync(0xffffffffu, ss, o);
    }
    __shared__ float ws[8], wss[8];
    int w = tid >> 5, l = tid & 31;
    if (l == 0) { ws[w] = s; wss[w] = ss; }
    __syncthreads();
    if (w == 0) {
        float a = (l < 8) ? ws[l]  : 0.f;
        float b = (l < 8) ? wss[l] : 0.f;
        #pragma unroll
        for (int o = 4; o > 0; o >>= 1) {
            a += __shfl_xor_sync(0xffffffffu, a, o);
            b += __shfl_xor_sync(0xffffffffu, b, o);
        }
        if (l == 0) { ws[0] = a; wss[0] = b; }
    }
    __syncthreads();
    float mu  = ws[0]  * (1.f / DIM);
    float var = wss[0] * (1.f / DIM) - mu * mu;
    float r   = rsqrtf(var + 1e-5f);
    float4 gm = reinterpret_cast<const float4*>(gamma)[tid];
    float4 bt = reinterpret_cast<const float4*>(beta)[tid];
    reinterpret_cast<__half2*>(g_h)[(size_t)row * (DIM/2) + 2*tid] =
        __floats2half2_rn((t.x - mu) * r * gm.x + bt.x, (t.y - mu) * r * gm.y + bt.y);
    reinterpret_cast<__half2*>(g_h)[(size_t)row * (DIM/2) + 2*tid+1] =
        __floats2half2_rn((t.z - mu) * r * gm.z + bt.z, (t.w - mu) * r * gm.w + bt.w);
}

// ---------------- FP16 GEMM-NT (BK=32, single-buffered, ldmatrix frags) ----------------
__global__ __launch_bounds__(256) void gemm_nt_f16(const __half* __restrict__ A,
                                                   const __half* __restrict__ B,
                                                   float* __restrict__ C,
                                                   int M, int N, int K,
                                                   long strideB, long strideC) {
    __shared__ __align__(16) uint32_t As[128 * 20];
    __shared__ __align__(16) uint32_t Bs[128 * 20];
    const __half* Bz = B + (size_t)blockIdx.z * strideB;
    float*        Cz = C + (size_t)blockIdx.z * strideC;
    int m0 = blockIdx.y * 128, n0 = blockIdx.x * 128;
    int tid = threadIdx.x, lane = tid & 31, wid = tid >> 5;
    int wm = (wid & 1) * 64, wn = (wid >> 1) * 32;
    int g = lane >> 2, t = lane & 3;
    float acc[4][4][4] = {};

    uint32_t aSm = (uint32_t)__cvta_generic_to_shared(As);
    uint32_t bSm = (uint32_t)__cvta_generic_to_shared(Bs);
    int la = lane & 7;
    int aRow = wm + ((lane >> 3) & 1) * 8 + la;     // + mf*16
    int aCol = ((lane >> 4) & 1) * 4;               // + ks
    int bRow = wn + ((lane >> 4) & 1) * 8 + la;     // + pr*16
    int bCol = ((lane >> 3) & 1) * 4;               // + ks

    for (int k0 = 0; k0 < K; k0 += 32) {
        #pragma unroll
        for (int i = 0; i < 2; i++) {
            int f = tid + 256 * i;
            int r = f >> 2, c4 = f & 3;
            float4 a = *reinterpret_cast<const float4*>(A  + (size_t)(m0 + r) * K + k0 + c4 * 8);
            *reinterpret_cast<float4*>(&As[r * 20 + c4 * 4]) = a;
            float4 b = *reinterpret_cast<const float4*>(Bz + (size_t)(n0 + r) * K + k0 + c4 * 8);
            *reinterpret_cast<float4*>(&Bs[r * 20 + c4 * 4]) = b;
        }
        __syncthreads();
        #pragma unroll
        for (int ks = 0; ks < 16; ks += 8) {
            uint32_t aR[4][4], bR[2][4];
            #pragma unroll
            for (int mf = 0; mf < 4; mf++)
                ldsm_x4(aR[mf], aSm + (uint32_t)(((aRow + mf * 16) * 20 + ks + aCol) * 4));
            #pragma unroll
            for (int pr = 0; pr < 2; pr++)
                ldsm_x4(bR[pr], bSm + (uint32_t)(((bRow + pr * 16) * 20 + ks + bCol) * 4));
            #pragma unroll
            for (int mf = 0; mf < 4; mf++)
                #pragma unroll
                for (int nf = 0; nf < 4; nf++)
                    mma_f16(acc[mf][nf], aR[mf], &bR[nf >> 1][(nf & 1) * 2]);
        }
        __syncthreads();
    }

    #pragma unroll
    for (int mf = 0; mf < 4; mf++)
        #pragma unroll
        for (int nf = 0; nf < 4; nf++) {
            int m = m0 + wm + mf * 16 + g;
            int n = n0 + wn + nf * 8 + 2 * t;
            *reinterpret_cast<float2*>(Cz + (size_t)m * N + n) =
                make_float2(acc[mf][nf][0], acc[mf][nf][1]);
            *reinterpret_cast<float2*>(Cz + (size_t)(m + 8) * N + n) =
                make_float2(acc[mf][nf][2], acc[mf][nf][3]);
        }
}

// ---------------- tiled depthwise causal conv (fp16 out, mma layouts) ----------------
__device__ const float* g_convw[18];
__global__ __launch_bounds__(256) void conv_kernel() {
    __shared__ float  s_in [64 * 72];     // [dh][col], col = n0-8 .. n0+63
    __shared__ __half s_out[64 * 72];     // p<2: [n][dh]; p==2: [dh][n]
    int n0 = blockIdx.x * 64;
    int ct = blockIdx.y;                  // 0..47
    int p  = ct >> 4, h = ct & 15;
    int b  = blockIdx.z;
    int g  = h >> 2;
    int tid = threadIdx.x;

    const float* src = g_qkv + ((size_t)(b * 3 + p) * INNER + h * 64) * SEQ;
    for (int idx = tid; idx < 64 * 72; idx += 256) {
        int dh = idx / 72, col = idx % 72;
        int m = n0 - 8 + col;
        s_in[idx] = (m >= 0) ? src[(size_t)dh * SEQ + m] : 0.f;
    }
    __syncthreads();

    int dh = tid >> 2, nb = (tid & 3) * 16;
    float scale = (p == 0) ? 0.125f : 1.0f;
    if (g == 0) {
        for (int s = 0; s < 16; s++) {
            int rel = nb + s;
            float acc = s_in[dh * 72 + 8 + rel] * scale;
            if (p < 2) s_out[rel * 72 + dh] = __float2half(acc);
            else       s_out[dh * 72 + rel] = __float2half(acc);
        }
    } else {
        int ksz = 2 * g + 1;
        int cg  = (h & 3) * 64 + dh;
        const float* w  = g_convw[p * 6 + (g - 1) * 2] + cg * ksz;
        float bias      = g_convw[p * 6 + (g - 1) * 2 + 1][cg];
        float wr[7];
        for (int tt = 0; tt < ksz; tt++) wr[tt] = w[tt];
        for (int s = 0; s < 16; s++) {
            int rel = nb + s;
            float acc = bias;
            int cbase = dh * 72 + 8 + rel - (ksz - 1);
            for (int tt = 0; tt < ksz; tt++) acc += wr[tt] * s_in[cbase + tt];
            acc *= scale;
            if (p < 2) s_out[rel * 72 + dh] = __float2half(acc);
            else       s_out[dh * 72 + rel] = __float2half(acc);
        }
    }
    __syncthreads();

    int row = tid >> 2, chunk = tid & 3;
    const uint4* sp = reinterpret_cast<const uint4*>(&s_out[row * 72 + chunk * 16]);
    __half* dst;
    if (p < 2) {
        __half* base = (p == 0) ? g_q16 : g_k16;
        dst = base + ((size_t)(b * HEADS + h) * SEQ + n0 + row) * DH + chunk * 16;
    } else {
        dst = g_v16 + ((size_t)(b * HEADS + h) * DH + row) * SEQ + n0 + chunk * 16;
    }
    reinterpret_cast<uint4*>(dst)[0] = sp[0];
    reinterpret_cast<uint4*>(dst)[1] = sp[1];
}

__global__ void set_convw(const float* a0, const float* a1, const float* a2, const float* a3,
                          const float* a4, const float* a5, const float* a6, const float* a7,
                          const float* a8, const float* a9, const float* a10, const float* a11,
                          const float* a12, const float* a13, const float* a14, const float* a15,
                          const float* a16, const float* a17) {
    g_convw[0]=a0; g_convw[1]=a1; g_convw[2]=a2; g_convw[3]=a3; g_convw[4]=a4; g_convw[5]=a5;
    g_convw[6]=a6; g_convw[7]=a7; g_convw[8]=a8; g_convw[9]=a9; g_convw[10]=a10; g_convw[11]=a11;
    g_convw[12]=a12; g_convw[13]=a13; g_convw[14]=a14; g_convw[15]=a15; g_convw[16]=a16; g_convw[17]=a17;
}

// ---------------- fp16 tensor-core flash attention (R9 shape + ldmatrix) ----------------
// Q,K [bh][n][dh]; V [bh][dh][n]. 64 rows/block, 64-col tiles, 4 warps.
// P in registers; K/V B-frags via ldmatrix.x4. Heavy CTAs first.
#define AST 72
__global__ __launch_bounds__(128) void attn_f16(const float* __restrict__ slopes) {
    __shared__ __align__(16) __half Ksh[64 * AST];   // [j][d]
    __shared__ __align__(16) __half Vsh[64 * AST];   // [d][j]

    int it = gridDim.x - 1 - blockIdx.x;             // heavy CTAs first
    int i0 = it * 64;
    int bh = blockIdx.y, b = bh >> 4, h = bh & 15;
    float slope = slopes[h];
    int tid = threadIdx.x, lane = tid & 31, w = tid >> 5;
    int g = lane >> 2, t = lane & 3;
    int mb = w * 16;
    const __half* Qg = g_q16 + (size_t)bh * SEQ * DH;
    const __half* Kg = g_k16 + (size_t)bh * SEQ * DH;
    const __half* Vg = g_v16 + (size_t)bh * DH * SEQ;

    uint32_t kSm = (uint32_t)__cvta_generic_to_shared(Ksh);
    uint32_t vSm = (uint32_t)__cvta_generic_to_shared(Vsh);
    int la = lane & 7;
    int bRowSel  = ((lane >> 4) & 1) * 8 + la;       // + pr*16
    int bHalfSel = ((lane >> 3) & 1) * 8;            // + ks*16

    // Q fragments straight from gmem
    uint32_t aQ[4][4];
    int iq0 = i0 + mb + g, iq1 = iq0 + 8;
    #pragma unroll
    for (int ks = 0; ks < 4; ks++) {
        int base = ks * 16 + 2 * t;
        aQ[ks][0] = *reinterpret_cast<const uint32_t*>(&Qg[(size_t)iq0 * DH + base]);
        aQ[ks][1] = *reinterpret_cast<const uint32_t*>(&Qg[(size_t)iq1 * DH + base]);
        aQ[ks][2] = *reinterpret_cast<const uint32_t*>(&Qg[(size_t)iq0 * DH + base + 8]);
        aQ[ks][3] = *reinterpret_cast<const uint32_t*>(&Qg[(size_t)iq1 * DH + base + 8]);
    }

    float o[8][4] = {};
    float m0 = -1e30f, m1 = -1e30f, l0 = 0.f, l1 = 0.f;

    for (int jt = 0; jt <= it; jt++) {
        int j0 = jt * 64;
        __syncthreads();
        {   // load K [j][d] and V [d][j] tiles (plain coalesced copies)
            int r = tid >> 1, c = (tid & 1) * 32;
            const uint4* ks_ = reinterpret_cast<const uint4*>(&Kg[(size_t)(j0 + r) * DH + c]);
            uint4* kd = reinterpret_cast<uint4*>(&Ksh[r * AST + c]);
            kd[0] = ks_[0]; kd[1] = ks_[1]; kd[2] = ks_[2]; kd[3] = ks_[3];
            const uint4* vs_ = reinterpret_cast<const uint4*>(&Vg[(size_t)r * SEQ + j0 + c]);
            uint4* vd = reinterpret_cast<uint4*>(&Vsh[r * AST + c]);
            vd[0] = vs_[0]; vd[1] = vs_[1]; vd[2] = vs_[2]; vd[3] = vs_[3];
        }
        __syncthreads();

        // S = Q K^T  (B-frags via ldmatrix)
        float sF[8][4] = {};
        #pragma unroll
        for (int ks = 0; ks < 4; ks++) {
            #pragma unroll
            for (int pr = 0; pr < 4; pr++) {
                uint32_t q[4];
                ldsm_x4(q, kSm + (uint32_t)(((pr * 16 + bRowSel) * AST + ks * 16 + bHalfSel) * 2));
                mma_f16(sF[2*pr],     aQ[ks], q);
                mma_f16(sF[2*pr + 1], aQ[ks], q + 2);
            }
        }

        // bias + causal mask + online softmax
        int ir0 = i0 + mb + g, ir1 = ir0 + 8;
        float mloc0 = -1e30f, mloc1 = -1e30f;
        #pragma unroll
        for (int nf = 0; nf < 8; nf++) {
            int jc = j0 + nf*8 + 2*t;
            float v0 = sF[nf][0] + slope * (float)(jc     - ir0);
            float v1 = sF[nf][1] + slope * (float)(jc + 1 - ir0);
            float v2 = sF[nf][2] + slope * (float)(jc     - ir1);
            float v3 = sF[nf][3] + slope * (float)(jc + 1 - ir1);
            if (jc     > ir0) v0 = -1e30f;
            if (jc + 1 > ir0) v1 = -1e30f;
            if (jc     > ir1) v2 = -1e30f;
            if (jc + 1 > ir1) v3 = -1e30f;
            sF[nf][0] = v0; sF[nf][1] = v1; sF[nf][2] = v2; sF[nf][3] = v3;
            mloc0 = fmaxf(mloc0, fmaxf(v0, v1));
            mloc1 = fmaxf(mloc1, fmaxf(v2, v3));
        }
        mloc0 = fmaxf(mloc0, __shfl_xor_sync(0xffffffffu, mloc0, 1));
        mloc0 = fmaxf(mloc0, __shfl_xor_sync(0xffffffffu, mloc0, 2));
        mloc1 = fmaxf(mloc1, __shfl_xor_sync(0xffffffffu, mloc1, 1));
        mloc1 = fmaxf(mloc1, __shfl_xor_sync(0xffffffffu, mloc1, 2));
        float mn0 = fmaxf(m0, mloc0), mn1 = fmaxf(m1, mloc1);
        float sc0 = __expf(m0 - mn0), sc1 = __expf(m1 - mn1);
        float sum0 = 0.f, sum1 = 0.f;
        #pragma unroll
        for (int nf = 0; nf < 8; nf++) {
            sF[nf][0] = __expf(sF[nf][0] - mn0); sum0 += sF[nf][0];
            sF[nf][1] = __expf(sF[nf][1] - mn0); sum0 += sF[nf][1];
            sF[nf][2] = __expf(sF[nf][2] - mn1); sum1 += sF[nf][2];
            sF[nf][3] = __expf(sF[nf][3] - mn1); sum1 += sF[nf][3];
        }
        sum0 += __shfl_xor_sync(0xffffffffu, sum0, 1);
        sum0 += __shfl_xor_sync(0xffffffffu, sum0, 2);
        sum1 += __shfl_xor_sync(0xffffffffu, sum1, 1);
        sum1 += __shfl_xor_sync(0xffffffffu, sum1, 2);
        l0 = l0 * sc0 + sum0; l1 = l1 * sc1 + sum1;
        m0 = mn0; m1 = mn1;
        #pragma unroll
        for (int nf = 0; nf < 8; nf++) {
            o[nf][0] *= sc0; o[nf][1] *= sc0;
            o[nf][2] *= sc1; o[nf][3] *= sc1;
        }

        // pack P into fp16 A-fragments (registers only)
        uint32_t aP[4][4];
        #pragma unroll
        for (int ks = 0; ks < 4; ks++) {
            aP[ks][0] = pack_h2(sF[2*ks  ][0], sF[2*ks  ][1]);
            aP[ks][1] = pack_h2(sF[2*ks  ][2], sF[2*ks  ][3]);
            aP[ks][2] = pack_h2(sF[2*ks+1][0], sF[2*ks+1][1]);
            aP[ks][3] = pack_h2(sF[2*ks+1][2], sF[2*ks+1][3]);
        }

        // O += P V  (B-frags via ldmatrix)
        #pragma unroll
        for (int ks = 0; ks < 4; ks++) {
            #pragma unroll
            for (int pr = 0; pr < 4; pr++) {
                uint32_t q[4];
                ldsm_x4(q, vSm + (uint32_t)(((pr * 16 + bRowSel) * AST + ks * 16 + bHalfSel) * 2));
                mma_f16(o[2*pr],     aP[ks], q);
                mma_f16(o[2*pr + 1], aP[ks], q + 2);
            }
        }
    }

    // normalize + write (B,N,INNER) as fp16
    float inv0 = 1.f / l0, inv1 = 1.f / l1;
    int r0 = i0 + mb + g;
    #pragma unroll
    for (int nf = 0; nf < 8; nf++) {
        int col = h * DH + nf*8 + 2*t;
        *reinterpret_cast<__half2*>(&g_ao[((size_t)b * SEQ + r0    ) * INNER + col]) =
            __floats2half2_rn(o[nf][0] * inv0, o[nf][1] * inv0);
        *reinterpret_cast<__half2*>(&g_ao[((size_t)b * SEQ + r0 + 8) * INNER + col]) =
            __floats2half2_rn(o[nf][2] * inv1, o[nf][3] * inv1);
    }
}

// ---------------- launch ----------------
extern "C" void kernel_launch(void* const* d_in, const int* in_sizes, int n_in,
                              void* d_out, int out_size) {
    const float* x      = (const float*)d_in[0];
    const float* gamma  = (const float*)d_in[1];
    const float* beta   = (const float*)d_in[2];
    const float* w_qkv  = (const float*)d_in[3];
    const float* slopes = (const float*)d_in[22];
    const float* w_out  = (const float*)d_in[23];

    __half *ph, *pao, *pwqkv, *pwout;
    float *pqkv;
    cudaGetSymbolAddress((void**)&ph,    g_h);
    cudaGetSymbolAddress((void**)&pqkv,  g_qkv);
    cudaGetSymbolAddress((void**)&pao,   g_ao);
    cudaGetSymbolAddress((void**)&pwqkv, g_wqkv);
    cudaGetSymbolAddress((void**)&pwout, g_wout);

    // 0) conv weight ptrs + fp16 weight conversion
    set_convw<<<1, 1>>>(
        (const float*)d_in[4],  (const float*)d_in[5],  (const float*)d_in[6],
        (const float*)d_in[7],  (const float*)d_in[8],  (const float*)d_in[9],
        (const float*)d_in[10], (const float*)d_in[11], (const float*)d_in[12],
        (const float*)d_in[13], (const float*)d_in[14], (const float*)d_in[15],
        (const float*)d_in[16], (const float*)d_in[17], (const float*)d_in[18],
        (const float*)d_in[19], (const float*)d_in[20], (const float*)d_in[21]);
    cvt_f16_kernel<<<(3*INNER*DIM/4 + 255)/256, 256>>>(w_qkv, pwqkv, 3*INNER*DIM/4);
    cvt_f16_kernel<<<(DIM*INNER/4   + 255)/256, 256>>>(w_out, pwout, DIM*INNER/4);

    // 1) LayerNorm (fp16 out)
    ln_kernel<<<BATCH * SEQ, 256>>>(x, gamma, beta);

    // 2) QKV GEMM (fp16 in, fp32 out)
    gemm_nt_f16<<<dim3(SEQ/128, 3*INNER/128, BATCH), 256>>>(
        pwqkv, ph, pqkv, 3*INNER, SEQ, DIM,
        (long)SEQ * DIM, (long)3 * INNER * SEQ);

    // 3) tiled depthwise causal convs -> fp16 q/k [n][dh], v [dh][n]
    conv_kernel<<<dim3(SEQ/64, 48, BATCH), 256>>>();

    // 4) fp16 tensor-core flash attention (ldmatrix, heavy CTAs first)
    attn_f16<<<dim3(SEQ/64, BATCH*HEADS), 128>>>(slopes);

    // 5) output projection (fp16 in, fp32 out)
    gemm_nt_f16<<<dim3(DIM/128, (BATCH*SEQ)/128, 1), 256>>>(
        pao, pwout, (float*)d_out, BATCH*SEQ, DIM, INNER, 0, 0);
}

// round 13
// speedup vs baseline: 1.1302x; 1.0126x over previous
#include <cuda_runtime.h>
#include <cuda_fp16.h>
#include <math.h>
#include <stdint.h>

#define BATCH 2
#define SEQ   2048
#define DIM   1024
#define HEADS 16
#define DH    64
#define INNER 1024

// ---------------- scratch (device globals; no allocs) ----------------
__device__ __half g_h  [BATCH*SEQ*DIM];           // LN output (fp16)
__device__ __half g_qkv[BATCH*3*INNER*SEQ];       // (B, 3*INNER, SEQ) fp16
__device__ __half g_q16[BATCH*HEADS*SEQ*DH];      // [b][h][n][dh], scaled
__device__ __half g_k16[BATCH*HEADS*SEQ*DH];      // [b][h][n][dh]
__device__ __half g_v16[BATCH*HEADS*DH*SEQ];      // [b][h][dh][n]
__device__ __half g_ao [BATCH*SEQ*INNER];         // attention out (fp16)
__device__ __half g_wqkv[3*INNER*DIM];            // fp16 weights
__device__ __half g_wout[DIM*INNER];

// ---------------- helpers ----------------
__device__ __forceinline__ void mma_f16(float* d, const uint32_t* a, const uint32_t* b) {
    asm volatile(
        "mma.sync.aligned.m16n8k16.row.col.f32.f16.f16.f32 "
        "{%0,%1,%2,%3},{%4,%5,%6,%7},{%8,%9},{%0,%1,%2,%3};"
        : "+f"(d[0]), "+f"(d[1]), "+f"(d[2]), "+f"(d[3])
        : "r"(a[0]), "r"(a[1]), "r"(a[2]), "r"(a[3]), "r"(b[0]), "r"(b[1]));
}
__device__ __forceinline__ void ldsm_x4(uint32_t* r, uint32_t saddr) {
    asm volatile("ldmatrix.sync.aligned.m8n8.x4.shared.b16 {%0,%1,%2,%3}, [%4];"
        : "=r"(r[0]), "=r"(r[1]), "=r"(r[2]), "=r"(r[3]) : "r"(saddr));
}
__device__ __forceinline__ uint32_t pack_h2(float a, float b) {
    __half2 p = __floats2half2_rn(a, b);
    return *reinterpret_cast<uint32_t*>(&p);
}
__device__ __forceinline__ void cp_async16(void* smem, const void* g) {
    uint32_t s = (uint32_t)__cvta_generic_to_shared(smem);
    asm volatile("cp.async.cg.shared.global [%0], [%1], 16;" :: "r"(s), "l"(g));
}
__device__ __forceinline__ void cp_commit() { asm volatile("cp.async.commit_group;"); }
template <int N>
__device__ __forceinline__ void cp_wait() { asm volatile("cp.async.wait_group %0;" :: "n"(N)); }

// ---------------- fp16 pre-convert (weights) ----------------
__global__ __launch_bounds__(256) void cvt_f16_kernel(const float* __restrict__ src,
                                                      __half* __restrict__ dst, int n4) {
    int i = blockIdx.x * 256 + threadIdx.x;
    if (i >= n4) return;
    float4 v = reinterpret_cast<const float4*>(src)[i];
    reinterpret_cast<__half2*>(dst)[2*i]   = __floats2half2_rn(v.x, v.y);
    reinterpret_cast<__half2*>(dst)[2*i+1] = __floats2half2_rn(v.z, v.w);
}

// ---------------- LayerNorm (writes fp16) ----------------
__global__ __launch_bounds__(256) void ln_kernel(const float* __restrict__ x,
                                                 const float* __restrict__ gamma,
                                                 const float* __restrict__ beta) {
    int row = blockIdx.x;
    int tid = threadIdx.x;
    const float4* xr = reinterpret_cast<const float4*>(x) + (size_t)row * (DIM/4);
    float4 t = xr[tid];
    float s  = t.x + t.y + t.z + t.w;
    float ss = t.x*t.x + t.y*t.y + t.z*t.z + t.w*t.w;
    #pragma unroll
    for (int o = 16; o > 0; o >>= 1) {
        s  += __shfl_xor_sync(0xffffffffu, s,  o);
        ss += __shfl_xor_sync(0xffffffffu, ss, o);
    }
    __shared__ float ws[8], wss[8];
    int w = tid >> 5, l = tid & 31;
    if (l == 0) { ws[w] = s; wss[w] = ss; }
    __syncthreads();
    if (w == 0) {
        float a = (l < 8) ? ws[l]  : 0.f;
        float b = (l < 8) ? wss[l] : 0.f;
        #pragma unroll
        for (int o = 4; o > 0; o >>= 1) {
            a += __shfl_xor_sync(0xffffffffu, a, o);
            b += __shfl_xor_sync(0xffffffffu, b, o);
        }
        if (l == 0) { ws[0] = a; wss[0] = b; }
    }
    __syncthreads();
    float mu  = ws[0]  * (1.f / DIM);
    float var = wss[0] * (1.f / DIM) - mu * mu;
    float r   = rsqrtf(var + 1e-5f);
    float4 gm = reinterpret_cast<const float4*>(gamma)[tid];
    float4 bt = reinterpret_cast<const float4*>(beta)[tid];
    reinterpret_cast<__half2*>(g_h)[(size_t)row * (DIM/2) + 2*tid] =
        __floats2half2_rn((t.x - mu) * r * gm.x + bt.x, (t.y - mu) * r * gm.y + bt.y);
    reinterpret_cast<__half2*>(g_h)[(size_t)row * (DIM/2) + 2*tid+1] =
        __floats2half2_rn((t.z - mu) * r * gm.z + bt.z, (t.w - mu) * r * gm.w + bt.w);
}

// ---------------- FP16 GEMM-NT (BK=32, ldmatrix frags, optional half out) ----------------
__global__ __launch_bounds__(256) void gemm_nt_f16(const __half* __restrict__ A,
                                                   const __half* __restrict__ B,
                                                   void* __restrict__ Cv,
                                                   int M, int N, int K,
                                                   long strideB, long strideC,
                                                   int halfOut) {
    __shared__ __align__(16) uint32_t As[128 * 20];
    __shared__ __align__(16) uint32_t Bs[128 * 20];
    const __half* Bz = B + (size_t)blockIdx.z * strideB;
    int m0 = blockIdx.y * 128, n0 = blockIdx.x * 128;
    int tid = threadIdx.x, lane = tid & 31, wid = tid >> 5;
    int wm = (wid & 1) * 64, wn = (wid >> 1) * 32;
    int g = lane >> 2, t = lane & 3;
    float acc[4][4][4] = {};

    uint32_t aSm = (uint32_t)__cvta_generic_to_shared(As);
    uint32_t bSm = (uint32_t)__cvta_generic_to_shared(Bs);
    int la = lane & 7;
    int aRow = wm + ((lane >> 3) & 1) * 8 + la;
    int aCol = ((lane >> 4) & 1) * 4;
    int bRow = wn + ((lane >> 4) & 1) * 8 + la;
    int bCol = ((lane >> 3) & 1) * 4;

    for (int k0 = 0; k0 < K; k0 += 32) {
        #pragma unroll
        for (int i = 0; i < 2; i++) {
            int f = tid + 256 * i;
            int r = f >> 2, c4 = f & 3;
            float4 a = *reinterpret_cast<const float4*>(A  + (size_t)(m0 + r) * K + k0 + c4 * 8);
            *reinterpret_cast<float4*>(&As[r * 20 + c4 * 4]) = a;
            float4 b = *reinterpret_cast<const float4*>(Bz + (size_t)(n0 + r) * K + k0 + c4 * 8);
            *reinterpret_cast<float4*>(&Bs[r * 20 + c4 * 4]) = b;
        }
        __syncthreads();
        #pragma unroll
        for (int ks = 0; ks < 16; ks += 8) {
            uint32_t aR[4][4], bR[2][4];
            #pragma unroll
            for (int mf = 0; mf < 4; mf++)
                ldsm_x4(aR[mf], aSm + (uint32_t)(((aRow + mf * 16) * 20 + ks + aCol) * 4));
            #pragma unroll
            for (int pr = 0; pr < 2; pr++)
                ldsm_x4(bR[pr], bSm + (uint32_t)(((bRow + pr * 16) * 20 + ks + bCol) * 4));
            #pragma unroll
            for (int mf = 0; mf < 4; mf++)
                #pragma unroll
                for (int nf = 0; nf < 4; nf++)
                    mma_f16(acc[mf][nf], aR[mf], &bR[nf >> 1][(nf & 1) * 2]);
        }
        __syncthreads();
    }

    if (halfOut) {
        __half* Cz = (__half*)Cv + (size_t)blockIdx.z * strideC;
        #pragma unroll
        for (int mf = 0; mf < 4; mf++)
            #pragma unroll
            for (int nf = 0; nf < 4; nf++) {
                int m = m0 + wm + mf * 16 + g;
                int n = n0 + wn + nf * 8 + 2 * t;
                *reinterpret_cast<__half2*>(Cz + (size_t)m * N + n) =
                    __floats2half2_rn(acc[mf][nf][0], acc[mf][nf][1]);
                *reinterpret_cast<__half2*>(Cz + (size_t)(m + 8) * N + n) =
                    __floats2half2_rn(acc[mf][nf][2], acc[mf][nf][3]);
            }
    } else {
        float* Cz = (float*)Cv + (size_t)blockIdx.z * strideC;
        #pragma unroll
        for (int mf = 0; mf < 4; mf++)
            #pragma unroll
            for (int nf = 0; nf < 4; nf++) {
                int m = m0 + wm + mf * 16 + g;
                int n = n0 + wn + nf * 8 + 2 * t;
                *reinterpret_cast<float2*>(Cz + (size_t)m * N + n) =
                    make_float2(acc[mf][nf][0], acc[mf][nf][1]);
                *reinterpret_cast<float2*>(Cz + (size_t)(m + 8) * N + n) =
                    make_float2(acc[mf][nf][2], acc[mf][nf][3]);
            }
    }
}

// ---------------- tiled depthwise causal conv (fp16 in/out, mma layouts) ----------------
__device__ const float* g_convw[18];
__global__ __launch_bounds__(256) void conv_kernel() {
    __shared__ float  s_in [64 * 72];     // [dh][col], col = n0-8 .. n0+63
    __shared__ __half s_out[64 * 72];     // p<2: [n][dh]; p==2: [dh][n]
    int n0 = blockIdx.x * 64;
    int ct = blockIdx.y;                  // 0..47
    int p  = ct >> 4, h = ct & 15;
    int b  = blockIdx.z;
    int g  = h >> 2;
    int tid = threadIdx.x;

    const __half* src = g_qkv + ((size_t)(b * 3 + p) * INNER + h * 64) * SEQ;
    for (int idx = tid; idx < 64 * 72; idx += 256) {
        int dh = idx / 72, col = idx % 72;
        int m = n0 - 8 + col;
        s_in[idx] = (m >= 0) ? __half2float(src[(size_t)dh * SEQ + m]) : 0.f;
    }
    __syncthreads();

    int dh = tid >> 2, nb = (tid & 3) * 16;
    float scale = (p == 0) ? 0.125f : 1.0f;
    if (g == 0) {
        for (int s = 0; s < 16; s++) {
            int rel = nb + s;
            float acc = s_in[dh * 72 + 8 + rel] * scale;
            if (p < 2) s_out[rel * 72 + dh] = __float2half(acc);
            else       s_out[dh * 72 + rel] = __float2half(acc);
        }
    } else {
        int ksz = 2 * g + 1;
        int cg  = (h & 3) * 64 + dh;
        const float* w  = g_convw[p * 6 + (g - 1) * 2] + cg * ksz;
        float bias      = g_convw[p * 6 + (g - 1) * 2 + 1][cg];
        float wr[7];
        for (int tt = 0; tt < ksz; tt++) wr[tt] = w[tt];
        for (int s = 0; s < 16; s++) {
            int rel = nb + s;
            float acc = bias;
            int cbase = dh * 72 + 8 + rel - (ksz - 1);
            for (int tt = 0; tt < ksz; tt++) acc += wr[tt] * s_in[cbase + tt];
            acc *= scale;
            if (p < 2) s_out[rel * 72 + dh] = __float2half(acc);
            else       s_out[dh * 72 + rel] = __float2half(acc);
        }
    }
    __syncthreads();

    int row = tid >> 2, chunk = tid & 3;
    const uint4* sp = reinterpret_cast<const uint4*>(&s_out[row * 72 + chunk * 16]);
    __half* dst;
    if (p < 2) {
        __half* base = (p == 0) ? g_q16 : g_k16;
        dst = base + ((size_t)(b * HEADS + h) * SEQ + n0 + row) * DH + chunk * 16;
    } else {
        dst = g_v16 + ((size_t)(b * HEADS + h) * DH + row) * SEQ + n0 + chunk * 16;
    }
    reinterpret_cast<uint4*>(dst)[0] = sp[0];
    reinterpret_cast<uint4*>(dst)[1] = sp[1];
}

__global__ void set_convw(const float* a0, const float* a1, const float* a2, const float* a3,
                          const float* a4, const float* a5, const float* a6, const float* a7,
                          const float* a8, const float* a9, const float* a10, const float* a11,
                          const float* a12, const float* a13, const float* a14, const float* a15,
                          const float* a16, const float* a17) {
    g_convw[0]=a0; g_convw[1]=a1; g_convw[2]=a2; g_convw[3]=a3; g_convw[4]=a4; g_convw[5]=a5;
    g_convw[6]=a6; g_convw[7]=a7; g_convw[8]=a8; g_convw[9]=a9; g_convw[10]=a10; g_convw[11]=a11;
    g_convw[12]=a12; g_convw[13]=a13; g_convw[14]=a14; g_convw[15]=a15; g_convw[16]=a16; g_convw[17]=a17;
}

// ---------------- fp16 tensor-core flash attention (ldmatrix + cp.async dbuf) ----------------
// Q,K [bh][n][dh]; V [bh][dh][n]. 64 rows/block, 64-col tiles, 4 warps, 2-buffer K/V.
// One __syncthreads per j-tile; prefetch overlaps with mma. Heavy CTAs first.
#define AST 72
#define ATILE (64 * AST)
__global__ __launch_bounds__(128) void attn_f16(const float* __restrict__ slopes) {
    __shared__ __align__(16) __half Ksh[2][ATILE];   // [j][d]
    __shared__ __align__(16) __half Vsh[2][ATILE];   // [d][j]

    int it = gridDim.x - 1 - blockIdx.x;             // heavy CTAs first
    int i0 = it * 64;
    int bh = blockIdx.y, b = bh >> 4, h = bh & 15;
    float slope = slopes[h];
    int tid = threadIdx.x, lane = tid & 31, w = tid >> 5;
    int g = lane >> 2, t = lane & 3;
    int mb = w * 16;
    const __half* Qg = g_q16 + (size_t)bh * SEQ * DH;
    const __half* Kg = g_k16 + (size_t)bh * SEQ * DH;
    const __half* Vg = g_v16 + (size_t)bh * DH * SEQ;

    int r_ld = tid >> 1, c_ld = (tid & 1) * 32;
    auto prefetch = [&](int j0, int st) {
        const __half* kp = Kg + (size_t)(j0 + r_ld) * DH + c_ld;
        __half* kd = &Ksh[st][r_ld * AST + c_ld];
        const __half* vp = Vg + (size_t)r_ld * SEQ + j0 + c_ld;
        __half* vd = &Vsh[st][r_ld * AST + c_ld];
        #pragma unroll
        for (int q = 0; q < 4; q++) {       // 4 x 16B = 32 halfs
            cp_async16(kd + q * 8, kp + q * 8);
            cp_async16(vd + q * 8, vp + q * 8);
        }
    };

    uint32_t kSm0 = (uint32_t)__cvta_generic_to_shared(&Ksh[0][0]);
    uint32_t vSm0 = (uint32_t)__cvta_generic_to_shared(&Vsh[0][0]);
    int la = lane & 7;
    int bRowSel  = ((lane >> 4) & 1) * 8 + la;       // + pr*16
    int bHalfSel = ((lane >> 3) & 1) * 8;            // + ks*16

    prefetch(0, 0); cp_commit();

    // Q fragments straight from gmem
    uint32_t aQ[4][4];
    int iq0 = i0 + mb + g, iq1 = iq0 + 8;
    #pragma unroll
    for (int ks = 0; ks < 4; ks++) {
        int base = ks * 16 + 2 * t;
        aQ[ks][0] = *reinterpret_cast<const uint32_t*>(&Qg[(size_t)iq0 * DH + base]);
        aQ[ks][1] = *reinterpret_cast<const uint32_t*>(&Qg[(size_t)iq1 * DH + base]);
        aQ[ks][2] = *reinterpret_cast<const uint32_t*>(&Qg[(size_t)iq0 * DH + base + 8]);
        aQ[ks][3] = *reinterpret_cast<const uint32_t*>(&Qg[(size_t)iq1 * DH + base + 8]);
    }
    cp_wait<0>();
    __syncthreads();                                  // tile 0 visible

    float o[8][4] = {};
    float m0 = -1e30f, m1 = -1e30f, l0 = 0.f, l1 = 0.f;

    for (int jt = 0; jt <= it; jt++) {
        int cur = jt & 1;
        int j0 = jt * 64;
        if (jt < it) { prefetch(j0 + 64, cur ^ 1); cp_commit(); }
        uint32_t kSm = kSm0 + (uint32_t)(cur * ATILE * 2);
        uint32_t vSm = vSm0 + (uint32_t)(cur * ATILE * 2);

        // S = Q K^T  (B-frags via ldmatrix)
        float sF[8][4] = {};
        #pragma unroll
        for (int ks = 0; ks < 4; ks++) {
            #pragma unroll
            for (int pr = 0; pr < 4; pr++) {
                uint32_t q[4];
                ldsm_x4(q, kSm + (uint32_t)(((pr * 16 + bRowSel) * AST + ks * 16 + bHalfSel) * 2));
                mma_f16(sF[2*pr],     aQ[ks], q);
                mma_f16(sF[2*pr + 1], aQ[ks], q + 2);
            }
        }

        // bias + causal mask + online softmax
        int ir0 = i0 + mb + g, ir1 = ir0 + 8;
        float mloc0 = -1e30f, mloc1 = -1e30f;
        #pragma unroll
        for (int nf = 0; nf < 8; nf++) {
            int jc = j0 + nf*8 + 2*t;
            float v0 = sF[nf][0] + slope * (float)(jc     - ir0);
            float v1 = sF[nf][1] + slope * (float)(jc + 1 - ir0);
            float v2 = sF[nf][2] + slope * (float)(jc     - ir1);
            float v3 = sF[nf][3] + slope * (float)(jc + 1 - ir1);
            if (jc     > ir0) v0 = -1e30f;
            if (jc + 1 > ir0) v1 = -1e30f;
            if (jc     > ir1) v2 = -1e30f;
            if (jc + 1 > ir1) v3 = -1e30f;
            sF[nf][0] = v0; sF[nf][1] = v1; sF[nf][2] = v2; sF[nf][3] = v3;
            mloc0 = fmaxf(mloc0, fmaxf(v0, v1));
            mloc1 = fmaxf(mloc1, fmaxf(v2, v3));
        }
        mloc0 = fmaxf(mloc0, __shfl_xor_sync(0xffffffffu, mloc0, 1));
        mloc0 = fmaxf(mloc0, __shfl_xor_sync(0xffffffffu, mloc0, 2));
        mloc1 = fmaxf(mloc1, __shfl_xor_sync(0xffffffffu, mloc1, 1));
        mloc1 = fmaxf(mloc1, __shfl_xor_sync(0xffffffffu, mloc1, 2));
        float mn0 = fmaxf(m0, mloc0), mn1 = fmaxf(m1, mloc1);
        float sc0 = __expf(m0 - mn0), sc1 = __expf(m1 - mn1);
        float sum0 = 0.f, sum1 = 0.f;
        #pragma unroll
        for (int nf = 0; nf < 8; nf++) {
            sF[nf][0] = __expf(sF[nf][0] - mn0); sum0 += sF[nf][0];
            sF[nf][1] = __expf(sF[nf][1] - mn0); sum0 += sF[nf][1];
            sF[nf][2] = __expf(sF[nf][2] - mn1); sum1 += sF[nf][2];
            sF[nf][3] = __expf(sF[nf][3] - mn1); sum1 += sF[nf][3];
        }
        sum0 += __shfl_xor_sync(0xffffffffu, sum0, 1);
        sum0 += __shfl_xor_sync(0xffffffffu, sum0, 2);
        sum1 += __shfl_xor_sync(0xffffffffu, sum1, 1);
        sum1 += __shfl_xor_sync(0xffffffffu, sum1, 2);
        l0 = l0 * sc0 + sum0; l1 = l1 * sc1 + sum1;
        m0 = mn0; m1 = mn1;
        #pragma unroll
        for (int nf = 0; nf < 8; nf++) {
            o[nf][0] *= sc0; o[nf][1] *= sc0;
            o[nf][2] *= sc1; o[nf][3] *= sc1;
        }

        // pack P into fp16 A-fragments (registers only)
        uint32_t aP[4][4];
        #pragma unroll
        for (int ks = 0; ks < 4; ks++) {
            aP[ks][0] = pack_h2(sF[2*ks  ][0], sF[2*ks  ][1]);
            aP[ks][1] = pack_h2(sF[2*ks  ][2], sF[2*ks  ][3]);
            aP[ks][2] = pack_h2(sF[2*ks+1][0], sF[2*ks+1][1]);
            aP[ks][3] = pack_h2(sF[2*ks+1][2], sF[2*ks+1][3]);
        }

        // O += P V  (B-frags via ldmatrix)
        #pragma unroll
        for (int ks = 0; ks < 4; ks++) {
            #pragma unroll
            for (int pr = 0; pr < 4; pr++) {
                uint32_t q[4];
                ldsm_x4(q, vSm + (uint32_t)(((pr * 16 + bRowSel) * AST + ks * 16 + bHalfSel) * 2));
                mma_f16(o[2*pr],     aP[ks], q);
                mma_f16(o[2*pr + 1], aP[ks], q + 2);
            }
        }

        if (jt < it) cp_wait<0>();
        __syncthreads();   // next tile visible; all warps done with alt buffer
    }

    // normalize + write (B,N,INNER) as fp16
    float inv0 = 1.f / l0, inv1 = 1.f / l1;
    int r0 = i0 + mb + g;
    #pragma unroll
    for (int nf = 0; nf < 8; nf++) {
        int col = h * DH + nf*8 + 2*t;
        *reinterpret_cast<__half2*>(&g_ao[((size_t)b * SEQ + r0    ) * INNER + col]) =
            __floats2half2_rn(o[nf][0] * inv0, o[nf][1] * inv0);
        *reinterpret_cast<__half2*>(&g_ao[((size_t)b * SEQ + r0 + 8) * INNER + col]) =
            __floats2half2_rn(o[nf][2] * inv1, o[nf][3] * inv1);
    }
}

// ---------------- launch ----------------
extern "C" void kernel_launch(void* const* d_in, const int* in_sizes, int n_in,
                              void* d_out, int out_size) {
    const float* x      = (const float*)d_in[0];
    const float* gamma  = (const float*)d_in[1];
    const float* beta   = (const float*)d_in[2];
    const float* w_qkv  = (const float*)d_in[3];
    const float* slopes = (const float*)d_in[22];
    const float* w_out  = (const float*)d_in[23];

    __half *ph, *pqkv, *pao, *pwqkv, *pwout;
    cudaGetSymbolAddress((void**)&ph,    g_h);
    cudaGetSymbolAddress((void**)&pqkv,  g_qkv);
    cudaGetSymbolAddress((void**)&pao,   g_ao);
    cudaGetSymbolAddress((void**)&pwqkv, g_wqkv);
    cudaGetSymbolAddress((void**)&pwout, g_wout);

    // 0) conv weight ptrs + fp16 weight conversion
    set_convw<<<1, 1>>>(
        (const float*)d_in[4],  (const float*)d_in[5],  (const float*)d_in[6],
        (const float*)d_in[7],  (const float*)d_in[8],  (const float*)d_in[9],
        (const float*)d_in[10], (const float*)d_in[11], (const float*)d_in[12],
        (const float*)d_in[13], (const float*)d_in[14], (const float*)d_in[15],
        (const float*)d_in[16], (const float*)d_in[17], (const float*)d_in[18],
        (const float*)d_in[19], (const float*)d_in[20], (const float*)d_in[21]);
    cvt_f16_kernel<<<(3*INNER*DIM/4 + 255)/256, 256>>>(w_qkv, pwqkv, 3*INNER*DIM/4);
    cvt_f16_kernel<<<(DIM*INNER/4   + 255)/256, 256>>>(w_out, pwout, DIM*INNER/4);

    // 1) LayerNorm (fp16 out)
    ln_kernel<<<BATCH * SEQ, 256>>>(x, gamma, beta);

    // 2) QKV GEMM (fp16 in, fp16 out)
    gemm_nt_f16<<<dim3(SEQ/128, 3*INNER/128, BATCH), 256>>>(
        pwqkv, ph, pqkv, 3*INNER, SEQ, DIM,
        (long)SEQ * DIM, (long)3 * INNER * SEQ, 1);

    // 3) tiled depthwise causal convs -> fp16 q/k [n][dh], v [dh][n]
    conv_kernel<<<dim3(SEQ/64, 48, BATCH), 256>>>();

    // 4) fp16 tensor-core flash attention (ldmatrix + cp.async, heavy first)
    attn_f16<<<dim3(SEQ/64, BATCH*HEADS), 128>>>(slopes);

    // 5) output projection (fp16 in, fp32 out)
    gemm_nt_f16<<<dim3(DIM/128, (BATCH*SEQ)/128, 1), 256>>>(
        pao, pwout, d_out, BATCH*SEQ, DIM, INNER, 0, 0, 0);
}